// round 8
// baseline (speedup 1.0000x reference)
#include <cuda_runtime.h>
#include <math.h>

#define BATCH 2
#define SEQ   4096
#define HID   768
#define NHEAD 12
#define HDIM  64
#define MROWS (BATCH * SEQ)   // 8192

// ---------------- scratch (device globals: allocation-free) ----------------
__device__ float g_Q[(size_t)MROWS * HID];
__device__ float g_K[(size_t)MROWS * HID];
__device__ float g_V[(size_t)MROWS * HID];
__device__ float g_C[(size_t)MROWS * HID];
__device__ float g_L[(size_t)BATCH * NHEAD * SEQ];

// ---------------- tf32 helpers ----------------
__device__ __forceinline__ unsigned f2tf(float x) {
    unsigned u;
    asm("cvt.rna.tf32.f32 %0, %1;" : "=r"(u) : "f"(x));
    return u;
}

__device__ __forceinline__ void mma_tf32(float* c, unsigned a0, unsigned a1,
                                         unsigned a2, unsigned a3,
                                         unsigned b0, unsigned b1) {
    asm volatile(
        "mma.sync.aligned.m16n8k8.row.col.f32.tf32.tf32.f32 "
        "{%0,%1,%2,%3}, {%4,%5,%6,%7}, {%8,%9}, {%0,%1,%2,%3};\n"
        : "+f"(c[0]), "+f"(c[1]), "+f"(c[2]), "+f"(c[3])
        : "r"(a0), "r"(a1), "r"(a2), "r"(a3), "r"(b0), "r"(b1));
}

// ---------------------------------------------------------------------------
// GEMM: Y[M,768] = X[M,768] @ W[768,768]^T + bias  (tf32 mma)
// CTA 128x128, 8 warps (4 m x 2 n), warp = 32x64, k-chunk 32.
// ---------------------------------------------------------------------------
#define GP 36
__global__ __launch_bounds__(256) void gemm_tf32(
    const float* __restrict__ X, const float* __restrict__ W,
    const float* __restrict__ bias, float* __restrict__ Y) {
    __shared__ unsigned Xs[128 * GP];
    __shared__ unsigned Ws[128 * GP];

    int tid = threadIdx.x, lane = tid & 31, wid = tid >> 5;
    int wm = wid & 3, wn = wid >> 2;
    int row0 = blockIdx.y * 128, col0 = blockIdx.x * 128;

    float acc[2][8][4];
#pragma unroll
    for (int mt = 0; mt < 2; mt++)
#pragma unroll
        for (int nt = 0; nt < 8; nt++)
#pragma unroll
            for (int j = 0; j < 4; j++) acc[mt][nt][j] = 0.f;

    int lr = tid >> 1, lc = (tid & 1) * 16;
    const float* xg = X + (size_t)(row0 + lr) * HID + lc;
    const float* wg = W + (size_t)(col0 + lr) * HID + lc;

    for (int k0 = 0; k0 < HID; k0 += 32) {
#pragma unroll
        for (int i = 0; i < 16; i += 4) {
            float4 v = *(const float4*)(xg + k0 + i);
            uint4 u = make_uint4(f2tf(v.x), f2tf(v.y), f2tf(v.z), f2tf(v.w));
            *(uint4*)&Xs[lr * GP + lc + i] = u;
            float4 w = *(const float4*)(wg + k0 + i);
            uint4 uw = make_uint4(f2tf(w.x), f2tf(w.y), f2tf(w.z), f2tf(w.w));
            *(uint4*)&Ws[lr * GP + lc + i] = uw;
        }
        __syncthreads();
#pragma unroll
        for (int kk = 0; kk < 4; kk++) {
            unsigned a[2][4];
#pragma unroll
            for (int mt = 0; mt < 2; mt++) {
                int r = wm * 32 + mt * 16 + (lane >> 2);
                int c = kk * 8 + (lane & 3);
                a[mt][0] = Xs[r * GP + c];
                a[mt][1] = Xs[(r + 8) * GP + c];
                a[mt][2] = Xs[r * GP + c + 4];
                a[mt][3] = Xs[(r + 8) * GP + c + 4];
            }
#pragma unroll
            for (int nt = 0; nt < 8; nt++) {
                int n = wn * 64 + nt * 8 + (lane >> 2);
                int c = kk * 8 + (lane & 3);
                unsigned b0 = Ws[n * GP + c], b1 = Ws[n * GP + c + 4];
                mma_tf32(acc[0][nt], a[0][0], a[0][1], a[0][2], a[0][3], b0, b1);
                mma_tf32(acc[1][nt], a[1][0], a[1][1], a[1][2], a[1][3], b0, b1);
            }
        }
        __syncthreads();
    }

#pragma unroll
    for (int mt = 0; mt < 2; mt++)
#pragma unroll
        for (int nt = 0; nt < 8; nt++) {
            int r = row0 + wm * 32 + mt * 16 + (lane >> 2);
            int c = col0 + wn * 64 + nt * 8 + 2 * (lane & 3);
            float bx = bias[c], by = bias[c + 1];
            float2 o0 = make_float2(acc[mt][nt][0] + bx, acc[mt][nt][1] + by);
            float2 o1 = make_float2(acc[mt][nt][2] + bx, acc[mt][nt][3] + by);
            *(float2*)&Y[(size_t)r * HID + c] = o0;
            *(float2*)&Y[(size_t)(r + 8) * HID + c] = o1;
        }
}

// ---------------------------------------------------------------------------
// Pass 1: row sums L only (no attn write). CTA: 128 q-rows, 8 warps x 16 rows.
// ---------------------------------------------------------------------------
#define AP 68
__global__ __launch_bounds__(256) void attn_lsum(
    const float* __restrict__ Q, const float* __restrict__ K,
    const int* __restrict__ mask, float* __restrict__ L) {
    extern __shared__ unsigned sm1[];
    unsigned* Qs = sm1;                    // 128*AP
    unsigned* Ks = sm1 + 128 * AP;         // 64*AP
    int* msk = (int*)(sm1 + 192 * AP);     // 64

    int tid = threadIdx.x, lane = tid & 31, wid = tid >> 5;
    int bh = blockIdx.y, b = bh / NHEAD, h = bh - b * NHEAD;
    int q0 = blockIdx.x * 128;

    {
        int r = tid >> 1, c0 = (tid & 1) * 32;
        const float* qg = Q + (size_t)(b * SEQ + q0 + r) * HID + h * HDIM + c0;
#pragma unroll
        for (int i = 0; i < 32; i += 4) {
            float4 v = *(const float4*)(qg + i);
            *(uint4*)&Qs[r * AP + c0 + i] =
                make_uint4(f2tf(v.x), f2tf(v.y), f2tf(v.z), f2tf(v.w));
        }
    }

    float sA = 0.f, sB = 0.f;
    const int* mg = mask + b * SEQ;
    const float* kgb = K + (size_t)(b * SEQ) * HID + h * HDIM;

    for (int kt = 0; kt < SEQ / 64; ++kt) {
        __syncthreads();
        {
            int r = tid >> 2, c0 = (tid & 3) * 16;
            const float* kg = kgb + (size_t)(kt * 64 + r) * HID + c0;
#pragma unroll
            for (int i = 0; i < 16; i += 4) {
                float4 v = *(const float4*)(kg + i);
                *(uint4*)&Ks[r * AP + c0 + i] =
                    make_uint4(f2tf(v.x), f2tf(v.y), f2tf(v.z), f2tf(v.w));
            }
            if (tid < 64) msk[tid] = mg[kt * 64 + tid];
        }
        __syncthreads();

        float acc[8][4];
#pragma unroll
        for (int nt = 0; nt < 8; nt++)
#pragma unroll
            for (int j = 0; j < 4; j++) acc[nt][j] = 0.f;

#pragma unroll
        for (int kk = 0; kk < 8; kk++) {
            int r = wid * 16 + (lane >> 2), c = kk * 8 + (lane & 3);
            unsigned a0 = Qs[r * AP + c], a1 = Qs[(r + 8) * AP + c];
            unsigned a2 = Qs[r * AP + c + 4], a3 = Qs[(r + 8) * AP + c + 4];
#pragma unroll
            for (int nt = 0; nt < 8; nt++) {
                int n = nt * 8 + (lane >> 2);
                unsigned b0 = Ks[n * AP + c], b1 = Ks[n * AP + c + 4];
                mma_tf32(acc[nt], a0, a1, a2, a3, b0, b1);
            }
        }

#pragma unroll
        for (int nt = 0; nt < 8; nt++) {
            int c = nt * 8 + 2 * (lane & 3);
            float m0 = msk[c] ? 1.f : 0.f, m1 = msk[c + 1] ? 1.f : 0.f;
            sA += m0 * __expf(acc[nt][0] * 0.125f) + m1 * __expf(acc[nt][1] * 0.125f);
            sB += m0 * __expf(acc[nt][2] * 0.125f) + m1 * __expf(acc[nt][3] * 0.125f);
        }
    }

    sA += __shfl_xor_sync(0xffffffffu, sA, 1);
    sA += __shfl_xor_sync(0xffffffffu, sA, 2);
    sB += __shfl_xor_sync(0xffffffffu, sB, 1);
    sB += __shfl_xor_sync(0xffffffffu, sB, 2);
    if ((lane & 3) == 0) {
        int r = q0 + wid * 16 + (lane >> 2);
        L[(size_t)bh * SEQ + r] = sA;
        L[(size_t)bh * SEQ + r + 8] = sB;
    }
}

// ---------------------------------------------------------------------------
// Pass 2: recompute scores, normalize, write attn weights (once), fuse P@V.
// ---------------------------------------------------------------------------
__global__ __launch_bounds__(256) void attn_pass2(
    const float* __restrict__ Q, const float* __restrict__ K,
    const float* __restrict__ V, const int* __restrict__ mask,
    const float* __restrict__ L, float* __restrict__ attn,
    float* __restrict__ Ctx) {
    extern __shared__ unsigned sm2[];
    unsigned* Qs = sm2;                    // 128*AP
    unsigned* Ks = sm2 + 128 * AP;         // 64*AP
    unsigned* Vs = sm2 + 192 * AP;         // 64*AP
    unsigned* Ps = sm2 + 256 * AP;         // 128*AP (16*AP per warp)
    int* msk = (int*)(sm2 + 384 * AP);     // 64

    int tid = threadIdx.x, lane = tid & 31, wid = tid >> 5;
    int bh = blockIdx.y, b = bh / NHEAD, h = bh - b * NHEAD;
    int q0 = blockIdx.x * 128;

    {
        int r = tid >> 1, c0 = (tid & 1) * 32;
        const float* qg = Q + (size_t)(b * SEQ + q0 + r) * HID + h * HDIM + c0;
#pragma unroll
        for (int i = 0; i < 32; i += 4) {
            float4 v = *(const float4*)(qg + i);
            *(uint4*)&Qs[r * AP + c0 + i] =
                make_uint4(f2tf(v.x), f2tf(v.y), f2tf(v.z), f2tf(v.w));
        }
    }

    int rA = q0 + wid * 16 + (lane >> 2);
    float liA = 1.0f / L[(size_t)bh * SEQ + rA];
    float liB = 1.0f / L[(size_t)bh * SEQ + rA + 8];

    float ctx[8][4];
#pragma unroll
    for (int nt = 0; nt < 8; nt++)
#pragma unroll
        for (int j = 0; j < 4; j++) ctx[nt][j] = 0.f;

    const int* mg = mask + b * SEQ;
    const float* kgb = K + (size_t)(b * SEQ) * HID + h * HDIM;
    const float* vgb = V + (size_t)(b * SEQ) * HID + h * HDIM;
    unsigned* Pw = Ps + wid * 16 * AP;
    float* abase = attn + ((size_t)bh * SEQ + q0 + wid * 16) * SEQ;

    for (int kt = 0; kt < SEQ / 64; ++kt) {
        __syncthreads();
        {
            int r = tid >> 2, c0 = (tid & 3) * 16;
            const float* kg = kgb + (size_t)(kt * 64 + r) * HID + c0;
            const float* vg = vgb + (size_t)(kt * 64 + r) * HID + c0;
#pragma unroll
            for (int i = 0; i < 16; i += 4) {
                float4 v = *(const float4*)(kg + i);
                *(uint4*)&Ks[r * AP + c0 + i] =
                    make_uint4(f2tf(v.x), f2tf(v.y), f2tf(v.z), f2tf(v.w));
                float4 w = *(const float4*)(vg + i);
                *(uint4*)&Vs[r * AP + c0 + i] =
                    make_uint4(f2tf(w.x), f2tf(w.y), f2tf(w.z), f2tf(w.w));
            }
            if (tid < 64) msk[tid] = mg[kt * 64 + tid];
        }
        __syncthreads();

        float acc[8][4];
#pragma unroll
        for (int nt = 0; nt < 8; nt++)
#pragma unroll
            for (int j = 0; j < 4; j++) acc[nt][j] = 0.f;

#pragma unroll
        for (int kk = 0; kk < 8; kk++) {
            int r = wid * 16 + (lane >> 2), c = kk * 8 + (lane & 3);
            unsigned a0 = Qs[r * AP + c], a1 = Qs[(r + 8) * AP + c];
            unsigned a2 = Qs[r * AP + c + 4], a3 = Qs[(r + 8) * AP + c + 4];
#pragma unroll
            for (int nt = 0; nt < 8; nt++) {
                int n = nt * 8 + (lane >> 2);
                unsigned b0 = Ks[n * AP + c], b1 = Ks[n * AP + c + 4];
                mma_tf32(acc[nt], a0, a1, a2, a3, b0, b1);
            }
        }

        // normalize, write attn (fp32), stage tf32 P for the V mma
        int rr = lane >> 2;
#pragma unroll
        for (int nt = 0; nt < 8; nt++) {
            int c = nt * 8 + 2 * (lane & 3);
            float m0 = msk[c] ? 1.f : 0.f, m1 = msk[c + 1] ? 1.f : 0.f;
            float w0 = m0 * __expf(acc[nt][0] * 0.125f) * liA;
            float w1 = m1 * __expf(acc[nt][1] * 0.125f) * liA;
            float w2 = m0 * __expf(acc[nt][2] * 0.125f) * liB;
            float w3 = m1 * __expf(acc[nt][3] * 0.125f) * liB;
            *(float2*)&abase[(size_t)rr * SEQ + kt * 64 + c] = make_float2(w0, w1);
            *(float2*)&abase[(size_t)(rr + 8) * SEQ + kt * 64 + c] = make_float2(w2, w3);
            Pw[rr * AP + c] = f2tf(w0);
            Pw[rr * AP + c + 1] = f2tf(w1);
            Pw[(rr + 8) * AP + c] = f2tf(w2);
            Pw[(rr + 8) * AP + c + 1] = f2tf(w3);
        }
        __syncwarp();

        // ctx += P @ V
#pragma unroll
        for (int kk = 0; kk < 8; kk++) {
            int c = kk * 8 + (lane & 3);
            unsigned a0 = Pw[rr * AP + c], a1 = Pw[(rr + 8) * AP + c];
            unsigned a2 = Pw[rr * AP + c + 4], a3 = Pw[(rr + 8) * AP + c + 4];
#pragma unroll
            for (int nt = 0; nt < 8; nt++) {
                unsigned b0 = Vs[(kk * 8 + (lane & 3)) * AP + nt * 8 + (lane >> 2)];
                unsigned b1 = Vs[(kk * 8 + (lane & 3) + 4) * AP + nt * 8 + (lane >> 2)];
                mma_tf32(ctx[nt], a0, a1, a2, a3, b0, b1);
            }
        }
        __syncwarp();
    }

#pragma unroll
    for (int nt = 0; nt < 8; nt++) {
        int rr = lane >> 2;
        int c = nt * 8 + 2 * (lane & 3);
        size_t base = (size_t)(b * SEQ + q0 + wid * 16 + rr) * HID + h * HDIM + c;
        *(float2*)&Ctx[base] = make_float2(ctx[nt][0], ctx[nt][1]);
        *(float2*)&Ctx[base + (size_t)8 * HID] = make_float2(ctx[nt][2], ctx[nt][3]);
    }
}

// ---------------------------------------------------------------------------
extern "C" void kernel_launch(void* const* d_in, const int* in_sizes, int n_in,
                              void* d_out, int out_size) {
    const float* hs   = (const float*)d_in[0];
    const int*   mask = (const int*)d_in[1];
    const float* Wq   = (const float*)d_in[2];
    const float* bq   = (const float*)d_in[3];
    const float* Wk   = (const float*)d_in[4];
    const float* bk   = (const float*)d_in[5];
    const float* Wv   = (const float*)d_in[6];
    const float* bv   = (const float*)d_in[7];
    const float* Wo   = (const float*)d_in[8];
    const float* bo   = (const float*)d_in[9];

    float* out  = (float*)d_out;                       // [B,S,768]
    float* attn = out + (size_t)MROWS * HID;           // [B,12,S,S]

    float *Qp, *Kp, *Vp, *Cp, *Lp;
    cudaGetSymbolAddress((void**)&Qp, g_Q);
    cudaGetSymbolAddress((void**)&Kp, g_K);
    cudaGetSymbolAddress((void**)&Vp, g_V);
    cudaGetSymbolAddress((void**)&Cp, g_C);
    cudaGetSymbolAddress((void**)&Lp, g_L);

    static int smem_set = 0;
    int smem1 = (192 * AP) * 4 + 64 * 4;               // ~52.5 KB
    int smem2 = (384 * AP) * 4 + 64 * 4;               // ~104.7 KB
    if (!smem_set) {
        cudaFuncSetAttribute(attn_lsum,
            cudaFuncAttributeMaxDynamicSharedMemorySize, smem1);
        cudaFuncSetAttribute(attn_pass2,
            cudaFuncAttributeMaxDynamicSharedMemorySize, smem2);
        smem_set = 1;
    }

    dim3 gg(HID / 128, MROWS / 128);   // (6, 64)
    gemm_tf32<<<gg, 256>>>(hs, Wq, bq, Qp);
    gemm_tf32<<<gg, 256>>>(hs, Wk, bk, Kp);
    gemm_tf32<<<gg, 256>>>(hs, Wv, bv, Vp);

    dim3 ga(SEQ / 128, BATCH * NHEAD); // (32, 24)
    attn_lsum<<<ga, 256, smem1>>>(Qp, Kp, mask, Lp);
    attn_pass2<<<ga, 256, smem2>>>(Qp, Kp, Vp, mask, Lp, attn, Cp);

    gemm_tf32<<<gg, 256>>>(Cp, Wo, bo, out);
}

// round 9
// speedup vs baseline: 1.0369x; 1.0369x over previous
#include <cuda_runtime.h>
#include <math.h>

#define BATCH 2
#define SEQ   4096
#define HID   768
#define NHEAD 12
#define HDIM  64
#define MROWS (BATCH * SEQ)   // 8192

#define AP 68   // attn smem pitch (words): stride%32==4 -> conflict-free ldmatrix
#define GP 36   // gemm smem pitch (words)

// ---------------- scratch (device globals: allocation-free) ----------------
__device__ float g_Q[(size_t)MROWS * HID];
__device__ float g_K[(size_t)MROWS * HID];
__device__ float g_V[(size_t)MROWS * HID];
__device__ float g_C[(size_t)MROWS * HID];
__device__ float g_L[(size_t)BATCH * NHEAD * SEQ];

// ---------------- helpers ----------------
__device__ __forceinline__ unsigned f2tf(float x) {
    unsigned u;
    asm("cvt.rna.tf32.f32 %0, %1;" : "=r"(u) : "f"(x));
    return u;
}

__device__ __forceinline__ void mma_tf32(float* c, unsigned a0, unsigned a1,
                                         unsigned a2, unsigned a3,
                                         unsigned b0, unsigned b1) {
    asm volatile(
        "mma.sync.aligned.m16n8k8.row.col.f32.tf32.tf32.f32 "
        "{%0,%1,%2,%3}, {%4,%5,%6,%7}, {%8,%9}, {%0,%1,%2,%3};\n"
        : "+f"(c[0]), "+f"(c[1]), "+f"(c[2]), "+f"(c[3])
        : "r"(a0), "r"(a1), "r"(a2), "r"(a3), "r"(b0), "r"(b1));
}

__device__ __forceinline__ void ldsm4(unsigned& r0, unsigned& r1,
                                      unsigned& r2, unsigned& r3, unsigned a) {
    asm volatile("ldmatrix.sync.aligned.m8n8.x4.shared.b16 {%0,%1,%2,%3}, [%4];"
                 : "=r"(r0), "=r"(r1), "=r"(r2), "=r"(r3) : "r"(a));
}

__device__ __forceinline__ unsigned smem_u32(const void* p) {
    return (unsigned)__cvta_generic_to_shared(p);
}

// lane address for an ldmatrix.x4 covering rows [row0,row0+16) x cols [col0,col0+8)
// (works for both A fragments and B fragment pairs in our layouts)
__device__ __forceinline__ unsigned fragA(unsigned base, int row0, int col0,
                                          int lane, int pitch) {
    int r = row0 + (lane & 15);
    int c = col0 + ((lane >> 4) << 2);
    return base + (unsigned)((r * pitch + c) << 2);
}

// ---------------------------------------------------------------------------
// GEMM: Y[M,768] = X[M,768] @ W[768,768]^T + bias  (tf32 mma + ldmatrix)
// CTA 128x128, 8 warps (4m x 2n), warp = 32x64, k-chunk 32.
// ---------------------------------------------------------------------------
__global__ __launch_bounds__(256) void gemm_tf32(
    const float* __restrict__ X, const float* __restrict__ W,
    const float* __restrict__ bias, float* __restrict__ Y) {
    __shared__ __align__(16) unsigned Xs[128 * GP];
    __shared__ __align__(16) unsigned Ws[128 * GP];

    int tid = threadIdx.x, lane = tid & 31, wid = tid >> 5;
    int wm = wid & 3, wn = wid >> 2;
    int row0 = blockIdx.y * 128, col0 = blockIdx.x * 128;

    float acc[2][8][4];
#pragma unroll
    for (int mt = 0; mt < 2; mt++)
#pragma unroll
        for (int nt = 0; nt < 8; nt++)
#pragma unroll
            for (int j = 0; j < 4; j++) acc[mt][nt][j] = 0.f;

    int lr = tid >> 1, lc = (tid & 1) * 16;
    const float* xg = X + (size_t)(row0 + lr) * HID + lc;
    const float* wg = W + (size_t)(col0 + lr) * HID + lc;
    unsigned xb = smem_u32(Xs), wb = smem_u32(Ws);

    for (int k0 = 0; k0 < HID; k0 += 32) {
#pragma unroll
        for (int i = 0; i < 16; i += 4) {
            float4 v = *(const float4*)(xg + k0 + i);
            *(uint4*)&Xs[lr * GP + lc + i] =
                make_uint4(f2tf(v.x), f2tf(v.y), f2tf(v.z), f2tf(v.w));
            float4 w = *(const float4*)(wg + k0 + i);
            *(uint4*)&Ws[lr * GP + lc + i] =
                make_uint4(f2tf(w.x), f2tf(w.y), f2tf(w.z), f2tf(w.w));
        }
        __syncthreads();
#pragma unroll
        for (int kk = 0; kk < 4; kk++) {
            unsigned a0[4], a1[4];
            ldsm4(a0[0], a0[1], a0[2], a0[3], fragA(xb, wm * 32, kk * 8, lane, GP));
            ldsm4(a1[0], a1[1], a1[2], a1[3], fragA(xb, wm * 32 + 16, kk * 8, lane, GP));
#pragma unroll
            for (int nt2 = 0; nt2 < 4; nt2++) {
                unsigned b0, b1, b2, b3;
                ldsm4(b0, b1, b2, b3, fragA(wb, wn * 64 + nt2 * 16, kk * 8, lane, GP));
                mma_tf32(acc[0][2 * nt2],     a0[0], a0[1], a0[2], a0[3], b0, b2);
                mma_tf32(acc[0][2 * nt2 + 1], a0[0], a0[1], a0[2], a0[3], b1, b3);
                mma_tf32(acc[1][2 * nt2],     a1[0], a1[1], a1[2], a1[3], b0, b2);
                mma_tf32(acc[1][2 * nt2 + 1], a1[0], a1[1], a1[2], a1[3], b1, b3);
            }
        }
        __syncthreads();
    }

#pragma unroll
    for (int mt = 0; mt < 2; mt++)
#pragma unroll
        for (int nt = 0; nt < 8; nt++) {
            int r = row0 + wm * 32 + mt * 16 + (lane >> 2);
            int c = col0 + wn * 64 + nt * 8 + 2 * (lane & 3);
            float bx = bias[c], by = bias[c + 1];
            *(float2*)&Y[(size_t)r * HID + c] =
                make_float2(acc[mt][nt][0] + bx, acc[mt][nt][1] + by);
            *(float2*)&Y[(size_t)(r + 8) * HID + c] =
                make_float2(acc[mt][nt][2] + bx, acc[mt][nt][3] + by);
        }
}

// ---------------------------------------------------------------------------
// Pass 1: row sums L only. Q fragments register-resident; K via ldmatrix.
// ---------------------------------------------------------------------------
__global__ __launch_bounds__(256) void attn_lsum(
    const float* __restrict__ Q, const float* __restrict__ K,
    const int* __restrict__ mask, float* __restrict__ L) {
    extern __shared__ __align__(16) unsigned sm1[];
    unsigned* Qs = sm1;            // 128*AP (reused as K tile after preload)
    unsigned* Ks = sm1;
    int* msk = (int*)(sm1 + 128 * AP);

    int tid = threadIdx.x, lane = tid & 31, wid = tid >> 5;
    int bh = blockIdx.y, b = bh / NHEAD, h = bh - b * NHEAD;
    int q0 = blockIdx.x * 128;

    {   // stage Q [128][64] (tf32)
        int r = tid >> 1, c0 = (tid & 1) * 32;
        const float* qg = Q + (size_t)(b * SEQ + q0 + r) * HID + h * HDIM + c0;
#pragma unroll
        for (int i = 0; i < 32; i += 4) {
            float4 v = *(const float4*)(qg + i);
            *(uint4*)&Qs[r * AP + c0 + i] =
                make_uint4(f2tf(v.x), f2tf(v.y), f2tf(v.z), f2tf(v.w));
        }
    }
    __syncthreads();

    unsigned qa[8][4];
    {
        unsigned qb = smem_u32(Qs);
#pragma unroll
        for (int kk = 0; kk < 8; kk++)
            ldsm4(qa[kk][0], qa[kk][1], qa[kk][2], qa[kk][3],
                  fragA(qb, wid * 16, kk * 8, lane, AP));
    }
    __syncthreads();   // Q smem now dead; reuse for K

    float sA = 0.f, sB = 0.f;
    const int* mg = mask + b * SEQ;
    const float* kgb = K + (size_t)(b * SEQ) * HID + h * HDIM;
    unsigned kb = smem_u32(Ks);

    for (int kt = 0; kt < SEQ / 64; ++kt) {
        {
            int r = tid >> 2, c0 = (tid & 3) * 16;
            const float* kg = kgb + (size_t)(kt * 64 + r) * HID + c0;
#pragma unroll
            for (int i = 0; i < 16; i += 4) {
                float4 v = *(const float4*)(kg + i);
                *(uint4*)&Ks[r * AP + c0 + i] =
                    make_uint4(f2tf(v.x), f2tf(v.y), f2tf(v.z), f2tf(v.w));
            }
            if (tid < 64) msk[tid] = mg[kt * 64 + tid];
        }
        __syncthreads();

#pragma unroll
        for (int g2 = 0; g2 < 4; g2++) {
            float acc[2][4];
#pragma unroll
            for (int gg = 0; gg < 2; gg++)
#pragma unroll
                for (int j = 0; j < 4; j++) acc[gg][j] = 0.f;
#pragma unroll
            for (int kk = 0; kk < 8; kk++) {
                unsigned b0, b1, b2, b3;
                ldsm4(b0, b1, b2, b3, fragA(kb, g2 * 16, kk * 8, lane, AP));
                mma_tf32(acc[0], qa[kk][0], qa[kk][1], qa[kk][2], qa[kk][3], b0, b2);
                mma_tf32(acc[1], qa[kk][0], qa[kk][1], qa[kk][2], qa[kk][3], b1, b3);
            }
#pragma unroll
            for (int gg = 0; gg < 2; gg++) {
                int c = (g2 * 2 + gg) * 8 + 2 * (lane & 3);
                float m0 = msk[c] ? 1.f : 0.f, m1 = msk[c + 1] ? 1.f : 0.f;
                sA += m0 * __expf(acc[gg][0] * 0.125f) + m1 * __expf(acc[gg][1] * 0.125f);
                sB += m0 * __expf(acc[gg][2] * 0.125f) + m1 * __expf(acc[gg][3] * 0.125f);
            }
        }
        __syncthreads();
    }

    sA += __shfl_xor_sync(0xffffffffu, sA, 1);
    sA += __shfl_xor_sync(0xffffffffu, sA, 2);
    sB += __shfl_xor_sync(0xffffffffu, sB, 1);
    sB += __shfl_xor_sync(0xffffffffu, sB, 2);
    if ((lane & 3) == 0) {
        int r = q0 + wid * 16 + (lane >> 2);
        L[(size_t)bh * SEQ + r] = sA;
        L[(size_t)bh * SEQ + r + 8] = sB;
    }
}

// ---------------------------------------------------------------------------
// Pass 2: recompute scores, normalize, write attn weights, fuse P@V.
// Q frags register-resident; P C-frag -> A-frag via warp shuffles (no smem).
// V staged transposed [d][key] so PV B-frags come from ldmatrix too.
// ---------------------------------------------------------------------------
__global__ __launch_bounds__(256) void attn_pass2(
    const float* __restrict__ Q, const float* __restrict__ K,
    const float* __restrict__ V, const int* __restrict__ mask,
    const float* __restrict__ L, float* __restrict__ attn,
    float* __restrict__ Ctx) {
    extern __shared__ __align__(16) unsigned sm2[];
    unsigned* Qs = sm2;                 // 128*AP, reused below
    unsigned* Ks = sm2;                 // 64*AP
    unsigned* Vt = sm2 + 64 * AP;       // 64*AP  (transposed: [d][key])
    int* msk = (int*)(sm2 + 128 * AP);

    int tid = threadIdx.x, lane = tid & 31, wid = tid >> 5;
    int bh = blockIdx.y, b = bh / NHEAD, h = bh - b * NHEAD;
    int q0 = blockIdx.x * 128;

    {   // stage Q
        int r = tid >> 1, c0 = (tid & 1) * 32;
        const float* qg = Q + (size_t)(b * SEQ + q0 + r) * HID + h * HDIM + c0;
#pragma unroll
        for (int i = 0; i < 32; i += 4) {
            float4 v = *(const float4*)(qg + i);
            *(uint4*)&Qs[r * AP + c0 + i] =
                make_uint4(f2tf(v.x), f2tf(v.y), f2tf(v.z), f2tf(v.w));
        }
    }
    __syncthreads();

    unsigned qa[8][4];
    {
        unsigned qb = smem_u32(Qs);
#pragma unroll
        for (int kk = 0; kk < 8; kk++)
            ldsm4(qa[kk][0], qa[kk][1], qa[kk][2], qa[kk][3],
                  fragA(qb, wid * 16, kk * 8, lane, AP));
    }
    __syncthreads();

    int rA = q0 + wid * 16 + (lane >> 2);
    float liA = 1.0f / L[(size_t)bh * SEQ + rA];
    float liB = 1.0f / L[(size_t)bh * SEQ + rA + 8];

    float ctx[8][4];
#pragma unroll
    for (int nt = 0; nt < 8; nt++)
#pragma unroll
        for (int j = 0; j < 4; j++) ctx[nt][j] = 0.f;

    const int* mg = mask + b * SEQ;
    const float* kgb = K + (size_t)(b * SEQ) * HID + h * HDIM;
    const float* vgb = V + (size_t)(b * SEQ) * HID + h * HDIM;
    unsigned kb = smem_u32(Ks), vb = smem_u32(Vt);
    float* abase = attn + ((size_t)bh * SEQ + q0 + wid * 16) * SEQ;
    int rr = lane >> 2, j = lane & 3;
    int s0 = (lane & ~3) | (j >> 1);
    int s1 = s0 | 2;
    bool odd = (j & 1);

    for (int kt = 0; kt < SEQ / 64; ++kt) {
        {
            int r = tid >> 2, c0 = (tid & 3) * 16;
            const float* kg = kgb + (size_t)(kt * 64 + r) * HID + c0;
            const float* vg = vgb + (size_t)(kt * 64 + r) * HID + c0;
#pragma unroll
            for (int i = 0; i < 16; i += 4) {
                float4 v = *(const float4*)(kg + i);
                *(uint4*)&Ks[r * AP + c0 + i] =
                    make_uint4(f2tf(v.x), f2tf(v.y), f2tf(v.z), f2tf(v.w));
                float4 w = *(const float4*)(vg + i);
                Vt[(c0 + i + 0) * AP + r] = f2tf(w.x);
                Vt[(c0 + i + 1) * AP + r] = f2tf(w.y);
                Vt[(c0 + i + 2) * AP + r] = f2tf(w.z);
                Vt[(c0 + i + 3) * AP + r] = f2tf(w.w);
            }
            if (tid < 64) msk[tid] = mg[kt * 64 + tid];
        }
        __syncthreads();

#pragma unroll
        for (int g2 = 0; g2 < 4; g2++) {
            float acc[2][4];
#pragma unroll
            for (int gg = 0; gg < 2; gg++)
#pragma unroll
                for (int q = 0; q < 4; q++) acc[gg][q] = 0.f;
#pragma unroll
            for (int kk = 0; kk < 8; kk++) {
                unsigned b0, b1, b2, b3;
                ldsm4(b0, b1, b2, b3, fragA(kb, g2 * 16, kk * 8, lane, AP));
                mma_tf32(acc[0], qa[kk][0], qa[kk][1], qa[kk][2], qa[kk][3], b0, b2);
                mma_tf32(acc[1], qa[kk][0], qa[kk][1], qa[kk][2], qa[kk][3], b1, b3);
            }
#pragma unroll
            for (int gg = 0; gg < 2; gg++) {
                int g = g2 * 2 + gg;
                int c = g * 8 + 2 * j;
                float m0 = msk[c] ? 1.f : 0.f, m1 = msk[c + 1] ? 1.f : 0.f;
                float w0 = m0 * __expf(acc[gg][0] * 0.125f) * liA;
                float w1 = m1 * __expf(acc[gg][1] * 0.125f) * liA;
                float w2 = m0 * __expf(acc[gg][2] * 0.125f) * liB;
                float w3 = m1 * __expf(acc[gg][3] * 0.125f) * liB;
                *(float2*)&abase[(size_t)rr * SEQ + kt * 64 + c] = make_float2(w0, w1);
                *(float2*)&abase[(size_t)(rr + 8) * SEQ + kt * 64 + c] = make_float2(w2, w3);

                unsigned u0 = f2tf(w0), u1 = f2tf(w1);
                unsigned u2 = f2tf(w2), u3 = f2tf(w3);
                // C-frag -> A-frag redistribution for P
                unsigned e00 = __shfl_sync(0xffffffffu, u0, s0);
                unsigned e01 = __shfl_sync(0xffffffffu, u1, s0);
                unsigned e10 = __shfl_sync(0xffffffffu, u2, s0);
                unsigned e11 = __shfl_sync(0xffffffffu, u3, s0);
                unsigned f00 = __shfl_sync(0xffffffffu, u0, s1);
                unsigned f01 = __shfl_sync(0xffffffffu, u1, s1);
                unsigned f10 = __shfl_sync(0xffffffffu, u2, s1);
                unsigned f11 = __shfl_sync(0xffffffffu, u3, s1);
                unsigned a0 = odd ? e01 : e00;
                unsigned a1 = odd ? e11 : e10;
                unsigned a2 = odd ? f01 : f00;
                unsigned a3 = odd ? f11 : f10;

                // ctx += P_g @ V_g
#pragma unroll
                for (int nt2 = 0; nt2 < 4; nt2++) {
                    unsigned v0, v1, v2, v3;
                    ldsm4(v0, v1, v2, v3, fragA(vb, nt2 * 16, g * 8, lane, AP));
                    mma_tf32(ctx[2 * nt2],     a0, a1, a2, a3, v0, v2);
                    mma_tf32(ctx[2 * nt2 + 1], a0, a1, a2, a3, v1, v3);
                }
            }
        }
        __syncthreads();
    }

#pragma unroll
    for (int nt = 0; nt < 8; nt++) {
        int c = nt * 8 + 2 * j;
        size_t base = (size_t)(b * SEQ + q0 + wid * 16 + rr) * HID + h * HDIM + c;
        *(float2*)&Ctx[base] = make_float2(ctx[nt][0], ctx[nt][1]);
        *(float2*)&Ctx[base + (size_t)8 * HID] = make_float2(ctx[nt][2], ctx[nt][3]);
    }
}

// ---------------------------------------------------------------------------
extern "C" void kernel_launch(void* const* d_in, const int* in_sizes, int n_in,
                              void* d_out, int out_size) {
    const float* hs   = (const float*)d_in[0];
    const int*   mask = (const int*)d_in[1];
    const float* Wq   = (const float*)d_in[2];
    const float* bq   = (const float*)d_in[3];
    const float* Wk   = (const float*)d_in[4];
    const float* bk   = (const float*)d_in[5];
    const float* Wv   = (const float*)d_in[6];
    const float* bv   = (const float*)d_in[7];
    const float* Wo   = (const float*)d_in[8];
    const float* bo   = (const float*)d_in[9];

    float* out  = (float*)d_out;                       // [B,S,768]
    float* attn = out + (size_t)MROWS * HID;           // [B,12,S,S]

    float *Qp, *Kp, *Vp, *Cp, *Lp;
    cudaGetSymbolAddress((void**)&Qp, g_Q);
    cudaGetSymbolAddress((void**)&Kp, g_K);
    cudaGetSymbolAddress((void**)&Vp, g_V);
    cudaGetSymbolAddress((void**)&Cp, g_C);
    cudaGetSymbolAddress((void**)&Lp, g_L);

    int smem_attn = (128 * AP) * 4 + 64 * 4;           // ~35 KB

    dim3 gg(HID / 128, MROWS / 128);   // (6, 64)
    gemm_tf32<<<gg, 256>>>(hs, Wq, bq, Qp);
    gemm_tf32<<<gg, 256>>>(hs, Wk, bk, Kp);
    gemm_tf32<<<gg, 256>>>(hs, Wv, bv, Vp);

    dim3 ga(SEQ / 128, BATCH * NHEAD); // (32, 24)
    attn_lsum<<<ga, 256, smem_attn>>>(Qp, Kp, mask, Lp);
    attn_pass2<<<ga, 256, smem_attn>>>(Qp, Kp, Vp, mask, Lp, attn, Cp);

    gemm_tf32<<<gg, 256>>>(Cp, Wo, bo, out);
}